// round 3
// baseline (speedup 1.0000x reference)
#include <cuda_runtime.h>
#include <cstdint>

#define Bb 2
#define Ss 2048
#define Dd 768
#define Hh 12
#define WIN 64

// ---------------- scratch (no allocations allowed) ----------------
__device__ float g_qkv[(size_t)Bb * Ss * 3 * Dd];     // [B*S, 2304]
__device__ float g_q[(size_t)Bb * Hh * Ss * 64];      // [B,H,S,64]
__device__ float g_k[(size_t)Bb * Hh * Ss * 64];
__device__ float g_v[(size_t)Bb * Hh * Ss * 64];
__device__ float g_att[(size_t)Bb * Ss * Dd];         // [B,S,768]

// ---------------- fp32 GEMM: C[m,n] = sum_k A[m,k] * B[n,k]  (both row-major, K contiguous)
__global__ __launch_bounds__(256, 2)
void sgemm_nt(const float* __restrict__ A, const float* __restrict__ B,
              float* __restrict__ C, int M, int N, int K)
{
    __shared__ float As[8][128];
    __shared__ float Bs[8][128];
    const int t  = threadIdx.x;
    const int bm = blockIdx.y, bn = blockIdx.x;
    const int lr = t >> 1;            // 0..127
    const int lk = (t & 1) * 4;       // 0 or 4
    const float* Ag = A + (size_t)(bm * 128 + lr) * K + lk;
    const float* Bg = B + (size_t)(bn * 128 + lr) * K + lk;
    const int tx = t & 15, ty = t >> 4;

    float acc[8][8];
#pragma unroll
    for (int i = 0; i < 8; i++)
#pragma unroll
        for (int j = 0; j < 8; j++) acc[i][j] = 0.f;

    for (int k0 = 0; k0 < K; k0 += 8) {
        float4 a4 = *(const float4*)(Ag + k0);
        float4 b4 = *(const float4*)(Bg + k0);
        As[lk + 0][lr] = a4.x; As[lk + 1][lr] = a4.y;
        As[lk + 2][lr] = a4.z; As[lk + 3][lr] = a4.w;
        Bs[lk + 0][lr] = b4.x; Bs[lk + 1][lr] = b4.y;
        Bs[lk + 2][lr] = b4.z; Bs[lk + 3][lr] = b4.w;
        __syncthreads();
#pragma unroll
        for (int kk = 0; kk < 8; kk++) {
            float ar[8], br[8];
            *(float4*)&ar[0] = *(const float4*)&As[kk][ty * 8];
            *(float4*)&ar[4] = *(const float4*)&As[kk][ty * 8 + 4];
            *(float4*)&br[0] = *(const float4*)&Bs[kk][tx * 8];
            *(float4*)&br[4] = *(const float4*)&Bs[kk][tx * 8 + 4];
#pragma unroll
            for (int i = 0; i < 8; i++)
#pragma unroll
                for (int j = 0; j < 8; j++) acc[i][j] += ar[i] * br[j];
        }
        __syncthreads();
    }

    float* Cg = C + (size_t)(bm * 128 + ty * 8) * N + bn * 128 + tx * 8;
#pragma unroll
    for (int i = 0; i < 8; i++) {
        *(float4*)&Cg[(size_t)i * N]     = make_float4(acc[i][0], acc[i][1], acc[i][2], acc[i][3]);
        *(float4*)&Cg[(size_t)i * N + 4] = make_float4(acc[i][4], acc[i][5], acc[i][6], acc[i][7]);
    }
}

// ---------------- RoPE + split into Q,K,V [B,H,S,64] ----------------
__global__ void rope_split(const float* __restrict__ qkv)
{
    int idx = blockIdx.x * blockDim.x + threadIdx.x;
    if (idx >= Bb * Ss * Hh * 32) return;
    int i  = idx & 31;
    int t2 = idx >> 5;
    int h  = t2 % Hh;
    int t3 = t2 / Hh;
    int s  = t3 % Ss;
    int b  = t3 / Ss;

    // inv_freq = 10000^{-(2i)/64}; pos = s (position_ids is arange by construction)
    float inv = exp2f(-(float)(2 * i) * (1.0f / 64.f) * 13.287712379549449f);
    float fr  = (float)s * inv;
    float cs, sn;
    sincosf(fr, &sn, &cs);

    size_t base = ((size_t)(b * Ss + s)) * (3 * Dd) + h * 64 + i;
    float q1 = qkv[base],        q2 = qkv[base + 32];
    float k1 = qkv[base + Dd],   k2 = qkv[base + Dd + 32];
    float v1 = qkv[base + 2*Dd], v2 = qkv[base + 2*Dd + 32];

    size_t ob = ((size_t)((b * Hh + h) * Ss + s)) * 64 + i;
    g_q[ob]      = q1 * cs - q2 * sn;
    g_q[ob + 32] = q2 * cs + q1 * sn;
    g_k[ob]      = k1 * cs - k2 * sn;
    g_k[ob + 32] = k2 * cs + k1 * sn;
    g_v[ob]      = v1;
    g_v[ob + 32] = v2;
}

// ---------------- sliding-window attention ----------------
#define QT 64
#define KT 192          // QT + 2*WIN
#define KST 68          // smem row stride (floats): 16B-aligned rows, conflict-free

__global__ __launch_bounds__(256, 1)
void attn_kernel(float* __restrict__ out)
{
    extern __shared__ float sm[];
    float* Ks = sm;                      // [KT][KST]
    float* Vs = sm + KT * KST;           // [KT][KST]
    float* Qs = sm + 2 * KT * KST;       // [QT][64]

    const int t  = threadIdx.x;
    const int qt = blockIdx.x * QT;
    const int h  = blockIdx.y, b = blockIdx.z;
    const float* Kg = g_k + (size_t)((b * Hh + h) * Ss) * 64;
    const float* Vg = g_v + (size_t)((b * Hh + h) * Ss) * 64;
    const float* Qg = g_q + (size_t)((b * Hh + h) * Ss) * 64;

    // stage K/V (zero-filled out of range) and Q (pre-scaled by 1/sqrt(64))
    for (int i = t; i < KT * 16; i += 256) {
        int row = i >> 4, c = (i & 15) * 4;
        int g = qt - WIN + row;
        float4 kv = make_float4(0.f, 0.f, 0.f, 0.f);
        float4 vv = make_float4(0.f, 0.f, 0.f, 0.f);
        if (g >= 0 && g < Ss) {
            kv = *(const float4*)(Kg + (size_t)g * 64 + c);
            vv = *(const float4*)(Vg + (size_t)g * 64 + c);
        }
        *(float4*)&Ks[row * KST + c] = kv;
        *(float4*)&Vs[row * KST + c] = vv;
    }
    for (int i = t; i < QT * 16; i += 256) {
        int row = i >> 4, c = (i & 15) * 4;
        float4 qv = *(const float4*)(Qg + (size_t)(qt + row) * 64 + c);
        qv.x *= 0.125f; qv.y *= 0.125f; qv.z *= 0.125f; qv.w *= 0.125f;
        *(float4*)&Qs[row * 64 + c] = qv;
    }
    __syncthreads();

    const int w = t >> 5, lane = t & 31;
    for (int r = 0; r < 8; r++) {
        int ql = w * 8 + r;
        float m = -1e30f, l = 0.f, acc0 = 0.f, acc1 = 0.f;
        int cbase = (ql >> 5) * 32;   // window [ql, ql+128] covered by exactly 5 chunks
#pragma unroll
        for (int c = 0; c < 5; c++) {
            int j0 = cbase + c * 32;
            int jl = j0 + lane;
            int g  = qt - WIN + jl;
            float sum = 0.f;
            {
                const float4* kr = (const float4*)&Ks[jl * KST];
                const float4* qr = (const float4*)&Qs[ql * 64];
#pragma unroll
                for (int d = 0; d < 16; d++) {
                    float4 kq = kr[d], qq = qr[d];
                    sum += qq.x * kq.x + qq.y * kq.y + qq.z * kq.z + qq.w * kq.w;
                }
            }
            bool valid = (g >= 0) && (g < Ss) && (jl >= ql) && (jl <= ql + 2 * WIN);
            float s = valid ? sum : -3.0e38f;

            float cm = s;
#pragma unroll
            for (int o = 16; o; o >>= 1) cm = fmaxf(cm, __shfl_xor_sync(0xffffffffu, cm, o));
            float nm   = fmaxf(m, cm);
            float corr = __expf(m - nm);          // 0 or 1 for sentinel cases, exact
            float p    = __expf(s - nm);
            float ps   = p;
#pragma unroll
            for (int o = 16; o; o >>= 1) ps += __shfl_xor_sync(0xffffffffu, ps, o);
            l = l * corr + ps;
            acc0 *= corr; acc1 *= corr;
#pragma unroll
            for (int j = 0; j < 32; j++) {
                float pj = __shfl_sync(0xffffffffu, p, j);
                acc0 += pj * Vs[(j0 + j) * KST + lane];
                acc1 += pj * Vs[(j0 + j) * KST + lane + 32];
            }
            m = nm;
        }
        float invl = 1.f / l;
        size_t ob = ((size_t)(b * Ss + qt + ql)) * Dd + h * 64;
        out[ob + lane]      = acc0 * invl;
        out[ob + lane + 32] = acc1 * invl;
    }
}

// ---------------- launch ----------------
extern "C" void kernel_launch(void* const* d_in, const int* in_sizes, int n_in,
                              void* d_out, int out_size)
{
    const float* hidden = (const float*)d_in[0];   // [B,S,D]
    const float* Wqkv   = (const float*)d_in[1];   // [3D, D]
    const float* Wo     = (const float*)d_in[2];   // [D, D]
    // d_in[3] = sliding_window_mask (implemented analytically)
    // d_in[4] = position_ids (== arange(S) by construction)
    float* out = (float*)d_out;

    float *qkv, *att;
    cudaGetSymbolAddress((void**)&qkv, g_qkv);
    cudaGetSymbolAddress((void**)&att, g_att);

    // 1) QKV projection: [4096,768] x [2304,768]^T -> [4096,2304]
    sgemm_nt<<<dim3(3 * Dd / 128, Bb * Ss / 128), 256>>>(hidden, Wqkv, qkv,
                                                         Bb * Ss, 3 * Dd, Dd);
    // 2) RoPE + split
    rope_split<<<(Bb * Ss * Hh * 32 + 255) / 256, 256>>>(qkv);

    // 3) sliding-window attention -> [B,S,768]
    const int SMEM = (2 * KT * KST + QT * 64) * (int)sizeof(float);
    cudaFuncSetAttribute(attn_kernel, cudaFuncAttributeMaxDynamicSharedMemorySize, SMEM);
    attn_kernel<<<dim3(Ss / QT, Hh, Bb), 256, SMEM>>>(att);

    // 4) output projection: [4096,768] x [768,768]^T -> [4096,768]
    sgemm_nt<<<dim3(Dd / 128, Bb * Ss / 128), 256>>>(att, Wo, out,
                                                     Bb * Ss, Dd, Dd);
}

// round 5
// speedup vs baseline: 1.7163x; 1.7163x over previous
#include <cuda_runtime.h>
#include <cstdint>

#define Bb 2
#define Ss 2048
#define Dd 768
#define Hh 12
#define WIN 64

// ---------------- scratch (no allocations allowed) ----------------
__device__ float g_qkv[(size_t)Bb * Ss * 3 * Dd];     // [B*S, 2304]
__device__ float g_q[(size_t)Bb * Hh * Ss * 64];      // [B,H,S,64]
__device__ float g_k[(size_t)Bb * Hh * Ss * 64];
__device__ float g_v[(size_t)Bb * Hh * Ss * 64];
__device__ float g_att[(size_t)Bb * Ss * Dd];         // [B,S,768]

// ================= tf32 tensor-core GEMM =================
// C[m,n] = sum_k A[m,k] * B[n,k]   (A:[M,K], B:[N,K] row-major)
// CTA tile 128x128, K-chunk 32, 8 warps (4x2), warp tile 32x64.
// Smem holds tiles in mma-fragment order -> conflict-free LDS.128/LDS.64.

__device__ __forceinline__ unsigned f2tf(float f) {
    unsigned u;
    asm("cvt.rna.tf32.f32 %0, %1;" : "=r"(u) : "f"(f));
    return u;
}

// 4x4 transpose among the 4 lanes of a quad (role r = lane&3).
__device__ __forceinline__ void xpose4(float4& v, int r) {
    float t0 = (r & 2) ? v.x : v.z;
    float t1 = (r & 2) ? v.y : v.w;
    t0 = __shfl_xor_sync(0xffffffffu, t0, 2);
    t1 = __shfl_xor_sync(0xffffffffu, t1, 2);
    if (r & 2) { v.x = t0; v.y = t1; } else { v.z = t0; v.w = t1; }
    float s0 = (r & 1) ? v.x : v.y;
    float s1 = (r & 1) ? v.z : v.w;
    s0 = __shfl_xor_sync(0xffffffffu, s0, 1);
    s1 = __shfl_xor_sync(0xffffffffu, s1, 1);
    if (r & 1) { v.x = s0; v.z = s1; } else { v.y = s0; v.w = s1; }
}

__device__ __forceinline__ void mma8(float* d, const uint4& a, const uint2& b) {
    asm volatile(
        "mma.sync.aligned.m16n8k8.row.col.f32.tf32.tf32.f32 "
        "{%0,%1,%2,%3}, {%4,%5,%6,%7}, {%8,%9}, {%0,%1,%2,%3};\n"
        : "+f"(d[0]), "+f"(d[1]), "+f"(d[2]), "+f"(d[3])
        : "r"(a.x), "r"(a.y), "r"(a.z), "r"(a.w), "r"(b.x), "r"(b.y));
}

__global__ __launch_bounds__(256, 1)
void tgemm_nt(const float* __restrict__ A, const float* __restrict__ B,
              float* __restrict__ C, int M, int N, int K)
{
    extern __shared__ unsigned sh[];
    unsigned* Asm = sh;            // 2 x 4096 uints (16KB each)
    unsigned* Bsm = sh + 8192;     // 2 x 4096 uints

    const int t    = threadIdx.x;
    const int w    = t >> 5;
    const int lane = t & 31;
    const int g    = lane >> 2;    // quad id 0..7
    const int r    = lane & 3;     // role in quad
    const int wm   = w & 3;        // warp m position (0..3)
    const int wn   = w >> 2;       // warp n position (0..1)
    const int bm   = blockIdx.y, bn = blockIdx.x;

    const float* Abase = A + (size_t)(bm * 128) * K;
    const float* Bbase = B + (size_t)(bn * 128) * K;

    // per-thread source coordinates for the cooperative loads
    const int a_mrow[1] = {0};
    (void)a_mrow;

    float c[2][8][4];
#pragma unroll
    for (int i = 0; i < 2; i++)
#pragma unroll
        for (int j = 0; j < 8; j++)
#pragma unroll
            for (int e = 0; e < 4; e++) c[i][j][e] = 0.f;

    float4 ra[4], rb[4];

    // ---- load chunk 0 into registers ----
#pragma unroll
    for (int it = 0; it < 4; it++) {
        int id = it * 8 + w;
        int mt = id & 7, kt = id >> 3;
        int row = mt * 16 + g + 8 * ((lane >> 1) & 1);
        int col = kt * 8 + (lane & 1) * 4;
        ra[it] = *(const float4*)(Abase + (size_t)row * K + col);
        int nt = id & 15, ktp = id >> 4;
        int brow = nt * 8 + g;
        int bcol = ktp * 16 + r * 4;
        rb[it] = *(const float4*)(Bbase + (size_t)brow * K + bcol);
    }

    int p = 0;
    for (int kc = 0; kc < K; kc += 32) {
        unsigned* Asp = Asm + p * 4096;
        unsigned* Bsp = Bsm + p * 4096;

        // ---- transpose to fragment order, cvt to tf32, store ----
#pragma unroll
        for (int it = 0; it < 4; it++) {
            int id = it * 8 + w;
            float4 v = ra[it];
            xpose4(v, r);
            // fragment reg order: (x,z,y,w)
            *(uint4*)(Asp + id * 128 + lane * 4) =
                make_uint4(f2tf(v.x), f2tf(v.z), f2tf(v.y), f2tf(v.w));

            float4 u = rb[it];
            xpose4(u, r);
            int nt = id & 15, ktp = id >> 4;
            unsigned* bp = Bsp + nt * 256 + ktp * 128 + lane * 2;
            *(uint2*)(bp)      = make_uint2(f2tf(u.x), f2tf(u.y));
            *(uint2*)(bp + 64) = make_uint2(f2tf(u.z), f2tf(u.w));
        }
        __syncthreads();

        // ---- prefetch next chunk into registers ----
        if (kc + 32 < K) {
            int kn = kc + 32;
#pragma unroll
            for (int it = 0; it < 4; it++) {
                int id = it * 8 + w;
                int mt = id & 7, kt = id >> 3;
                int row = mt * 16 + g + 8 * ((lane >> 1) & 1);
                int col = kn + kt * 8 + (lane & 1) * 4;
                ra[it] = *(const float4*)(Abase + (size_t)row * K + col);
                int nt = id & 15, ktp = id >> 4;
                int brow = nt * 8 + g;
                int bcol = kn + ktp * 16 + r * 4;
                rb[it] = *(const float4*)(Bbase + (size_t)brow * K + bcol);
            }
        }

        // ---- mma over 4 k-steps of 8 ----
#pragma unroll
        for (int kt = 0; kt < 4; kt++) {
            uint4 a0 = *(const uint4*)(Asp + (kt * 8 + wm * 2 + 0) * 128 + lane * 4);
            uint4 a1 = *(const uint4*)(Asp + (kt * 8 + wm * 2 + 1) * 128 + lane * 4);
            uint2 bb[8];
#pragma unroll
            for (int j = 0; j < 8; j++)
                bb[j] = *(const uint2*)(Bsp + (wn * 8 + j) * 256 + kt * 64 + lane * 2);
#pragma unroll
            for (int j = 0; j < 8; j++) {
                mma8(c[0][j], a0, bb[j]);
                mma8(c[1][j], a1, bb[j]);
            }
        }
        p ^= 1;
    }

    // ---- epilogue ----
    float* Cp = C + (size_t)(bm * 128) * N + bn * 128;
#pragma unroll
    for (int i = 0; i < 2; i++) {
#pragma unroll
        for (int j = 0; j < 8; j++) {
            int row = (wm * 2 + i) * 16 + g;
            int col = (wn * 8 + j) * 8 + r * 2;
            *(float2*)(Cp + (size_t)row * N + col) =
                make_float2(c[i][j][0], c[i][j][1]);
            *(float2*)(Cp + (size_t)(row + 8) * N + col) =
                make_float2(c[i][j][2], c[i][j][3]);
        }
    }
}

// ---------------- RoPE + split into Q,K,V [B,H,S,64] ----------------
__global__ void rope_split(const float* __restrict__ qkv)
{
    int idx = blockIdx.x * blockDim.x + threadIdx.x;
    if (idx >= Bb * Ss * Hh * 32) return;
    int i  = idx & 31;
    int t2 = idx >> 5;
    int h  = t2 % Hh;
    int t3 = t2 / Hh;
    int s  = t3 % Ss;
    int b  = t3 / Ss;

    float inv = exp2f(-(float)(2 * i) * (1.0f / 64.f) * 13.287712379549449f);
    float fr  = (float)s * inv;
    float cs, sn;
    sincosf(fr, &sn, &cs);

    size_t base = ((size_t)(b * Ss + s)) * (3 * Dd) + h * 64 + i;
    float q1 = qkv[base],        q2 = qkv[base + 32];
    float k1 = qkv[base + Dd],   k2 = qkv[base + Dd + 32];
    float v1 = qkv[base + 2*Dd], v2 = qkv[base + 2*Dd + 32];

    size_t ob = ((size_t)((b * Hh + h) * Ss + s)) * 64 + i;
    g_q[ob]      = q1 * cs - q2 * sn;
    g_q[ob + 32] = q2 * cs + q1 * sn;
    g_k[ob]      = k1 * cs - k2 * sn;
    g_k[ob + 32] = k2 * cs + k1 * sn;
    g_v[ob]      = v1;
    g_v[ob + 32] = v2;
}

// ---------------- sliding-window attention ----------------
#define QT 64
#define KT 192          // QT + 2*WIN
#define KST 68          // smem row stride (floats)

__global__ __launch_bounds__(256, 1)
void attn_kernel(float* __restrict__ out)
{
    extern __shared__ float sm[];
    float* Ks = sm;                      // [KT][KST]
    float* Vs = sm + KT * KST;           // [KT][KST]
    float* Qs = sm + 2 * KT * KST;       // [QT][64]

    const int t  = threadIdx.x;
    const int qt = blockIdx.x * QT;
    const int h  = blockIdx.y, b = blockIdx.z;
    const float* Kg = g_k + (size_t)((b * Hh + h) * Ss) * 64;
    const float* Vg = g_v + (size_t)((b * Hh + h) * Ss) * 64;
    const float* Qg = g_q + (size_t)((b * Hh + h) * Ss) * 64;

    for (int i = t; i < KT * 16; i += 256) {
        int row = i >> 4, c = (i & 15) * 4;
        int g = qt - WIN + row;
        float4 kv = make_float4(0.f, 0.f, 0.f, 0.f);
        float4 vv = make_float4(0.f, 0.f, 0.f, 0.f);
        if (g >= 0 && g < Ss) {
            kv = *(const float4*)(Kg + (size_t)g * 64 + c);
            vv = *(const float4*)(Vg + (size_t)g * 64 + c);
        }
        *(float4*)&Ks[row * KST + c] = kv;
        *(float4*)&Vs[row * KST + c] = vv;
    }
    for (int i = t; i < QT * 16; i += 256) {
        int row = i >> 4, c = (i & 15) * 4;
        float4 qv = *(const float4*)(Qg + (size_t)(qt + row) * 64 + c);
        qv.x *= 0.125f; qv.y *= 0.125f; qv.z *= 0.125f; qv.w *= 0.125f;
        *(float4*)&Qs[row * 64 + c] = qv;
    }
    __syncthreads();

    const int w = t >> 5, lane = t & 31;
    for (int r = 0; r < 8; r++) {
        int ql = w * 8 + r;
        float m = -1e30f, l = 0.f, acc0 = 0.f, acc1 = 0.f;
        int cbase = (ql >> 5) * 32;
#pragma unroll
        for (int c = 0; c < 5; c++) {
            int j0 = cbase + c * 32;
            int jl = j0 + lane;
            int g  = qt - WIN + jl;
            float sum = 0.f;
            {
                const float4* kr = (const float4*)&Ks[jl * KST];
                const float4* qr = (const float4*)&Qs[ql * 64];
#pragma unroll
                for (int d = 0; d < 16; d++) {
                    float4 kq = kr[d], qq = qr[d];
                    sum += qq.x * kq.x + qq.y * kq.y + qq.z * kq.z + qq.w * kq.w;
                }
            }
            bool valid = (g >= 0) && (g < Ss) && (jl >= ql) && (jl <= ql + 2 * WIN);
            float s = valid ? sum : -3.0e38f;

            float cm = s;
#pragma unroll
            for (int o = 16; o; o >>= 1) cm = fmaxf(cm, __shfl_xor_sync(0xffffffffu, cm, o));
            float nm   = fmaxf(m, cm);
            float corr = __expf(m - nm);
            float p    = __expf(s - nm);
            float ps   = p;
#pragma unroll
            for (int o = 16; o; o >>= 1) ps += __shfl_xor_sync(0xffffffffu, ps, o);
            l = l * corr + ps;
            acc0 *= corr; acc1 *= corr;
#pragma unroll
            for (int j = 0; j < 32; j++) {
                float pj = __shfl_sync(0xffffffffu, p, j);
                acc0 += pj * Vs[(j0 + j) * KST + lane];
                acc1 += pj * Vs[(j0 + j) * KST + lane + 32];
            }
            m = nm;
        }
        float invl = 1.f / l;
        size_t ob = ((size_t)(b * Ss + qt + ql)) * Dd + h * 64;
        out[ob + lane]      = acc0 * invl;
        out[ob + lane + 32] = acc1 * invl;
    }
}

// ---------------- launch ----------------
extern "C" void kernel_launch(void* const* d_in, const int* in_sizes, int n_in,
                              void* d_out, int out_size)
{
    const float* hidden = (const float*)d_in[0];   // [B,S,D]
    const float* Wqkv   = (const float*)d_in[1];   // [3D, D]
    const float* Wo     = (const float*)d_in[2];   // [D, D]
    float* out = (float*)d_out;

    float *qkv, *att;
    cudaGetSymbolAddress((void**)&qkv, g_qkv);
    cudaGetSymbolAddress((void**)&att, g_att);

    const int GSMEM = 16384 * (int)sizeof(unsigned);   // 64KB double-buffered tiles
    cudaFuncSetAttribute(tgemm_nt, cudaFuncAttributeMaxDynamicSharedMemorySize, GSMEM);

    // 1) QKV projection: [4096,768] x [2304,768]^T -> [4096,2304]
    tgemm_nt<<<dim3(3 * Dd / 128, Bb * Ss / 128), 256, GSMEM>>>(hidden, Wqkv, qkv,
                                                                Bb * Ss, 3 * Dd, Dd);
    // 2) RoPE + split
    rope_split<<<(Bb * Ss * Hh * 32 + 255) / 256, 256>>>(qkv);

    // 3) sliding-window attention -> [B,S,768]
    const int SMEM = (2 * KT * KST + QT * 64) * (int)sizeof(float);
    cudaFuncSetAttribute(attn_kernel, cudaFuncAttributeMaxDynamicSharedMemorySize, SMEM);
    attn_kernel<<<dim3(Ss / QT, Hh, Bb), 256, SMEM>>>(att);

    // 4) output projection: [4096,768] x [768,768]^T -> [4096,768]
    tgemm_nt<<<dim3(Dd / 128, Bb * Ss / 128), 256, GSMEM>>>(att, Wo, out,
                                                            Bb * Ss, Dd, Dd);
}